// round 1
// baseline (speedup 1.0000x reference)
#include <cuda_runtime.h>

// Problem shape (fixed for this benchmark):
//   x: (B=4, C2=64, H=256, W=512) fp32 ; max_disp D=64 ; C = 32
//   out: (B=4, D=64, H=256, W=512) fp32
//   out[b,d,h,w] = (1/C) * sum_c L[b,c,h,w] * R[b,c,h,w-d]   (R zero-padded left)

#define BB   4
#define CC   32
#define HH   256
#define WW   512
#define DD   64
#define RPAD 64
#define RW   (WW + RPAD)   // 576 floats per padded R row

#define NTHREADS 512

// Shared: L[32][512] + R[32][576]  = 65536 + 73728 = 139264 bytes
#define SMEM_BYTES ((CC * WW + CC * RW) * 4)

__global__ __launch_bounds__(NTHREADS, 1)
void disp_corr_kernel(const float* __restrict__ x, float* __restrict__ out) {
    extern __shared__ float smem[];
    float* Ls = smem;             // [CC][WW]
    float* Rs = smem + CC * WW;   // [CC][RW], first RPAD floats of each row are zero

    const int bx  = blockIdx.x;      // 0 .. B*H-1
    const int b   = bx >> 8;         // / 256
    const int h   = bx & 255;        // % 256
    const int tid = threadIdx.x;

    const size_t chw = (size_t)HH * WW;
    const float* xb = x + ((size_t)b * (2 * CC) * HH + (size_t)h * 1) * 0; // placeholder avoid miscompute
    // x[b, c, h, w] = x[ ((b*64 + c)*H + h)*W + w ]
    const float* xL = x + (((size_t)b * (2 * CC) + 0 ) * HH + h) * WW;
    const float* xR = x + (((size_t)b * (2 * CC) + CC) * HH + h) * WW;
    (void)xb;

    // ---- Stage L and R rows into shared memory (float4, coalesced) ----
    // 32 channels * 128 float4 per row = 4096 float4 each for L and R.
    for (int it = tid; it < CC * (WW / 4); it += NTHREADS) {
        const int c  = it >> 7;           // / 128
        const int w4 = it & 127;          // % 128
        float4 v = ((const float4*)(xL + (size_t)c * chw))[w4];
        ((float4*)(Ls + c * WW))[w4] = v;
        float4 u = ((const float4*)(xR + (size_t)c * chw))[w4];
        ((float4*)(Rs + c * RW + RPAD))[w4] = u;
    }
    // Zero the left pad: 32 * 16 float4
    for (int it = tid; it < CC * (RPAD / 4); it += NTHREADS) {
        const int c  = it >> 4;           // / 16
        const int w4 = it & 15;           // % 16
        ((float4*)(Rs + c * RW))[w4] = make_float4(0.f, 0.f, 0.f, 0.f);
    }
    __syncthreads();

    // ---- Each thread computes an 8(w) x 8(d) output tile ----
    // 512 threads * 64 outputs = 32768 = D*W (exactly one tile per thread)
    const int w_tile = tid & 63;     // 0..63 -> w0 = 8*w_tile
    const int d_tile = tid >> 6;     // 0..7  -> d0 = 8*d_tile
    const int w0 = w_tile << 3;
    const int d0 = d_tile << 3;
    // R window needed: Rs[c][RPAD + w - d] for w in [w0,w0+7], d in [d0,d0+7]
    //   -> indices RPAD + w0 - d0 - 7 .. RPAD + w0 - d0 + 7 ; load aligned 16 floats
    const int rbase = RPAD + w0 - d0 - 8;   // multiple of 8 floats -> 32B aligned, in [0, 560]

    float acc[8][8];
#pragma unroll
    for (int i = 0; i < 8; ++i)
#pragma unroll
        for (int j = 0; j < 8; ++j)
            acc[i][j] = 0.f;

#pragma unroll 4
    for (int c = 0; c < CC; ++c) {
        const float4* lp = (const float4*)(Ls + c * WW + w0);
        const float4 l0 = lp[0];
        const float4 l1 = lp[1];
        const float4* rp = (const float4*)(Rs + c * RW + rbase);
        const float4 r0 = rp[0];
        const float4 r1 = rp[1];
        const float4 r2 = rp[2];
        const float4 r3 = rp[3];

        const float l[8]  = { l0.x, l0.y, l0.z, l0.w, l1.x, l1.y, l1.z, l1.w };
        const float r[16] = { r0.x, r0.y, r0.z, r0.w, r1.x, r1.y, r1.z, r1.w,
                              r2.x, r2.y, r2.z, r2.w, r3.x, r3.y, r3.z, r3.w };

#pragma unroll
        for (int i = 0; i < 8; ++i) {
#pragma unroll
            for (int j = 0; j < 8; ++j) {
                // w = w0+i, d = d0+j  ->  R index RPAD + (w0+i) - (d0+j) = rbase + 8 + i - j
                acc[i][j] += l[i] * r[i - j + 8];
            }
        }
    }

    // ---- Write out: out[ ((b*D + d)*H + h)*W + w ], float4 coalesced ----
    const float inv_c = 1.0f / (float)CC;
#pragma unroll
    for (int j = 0; j < 8; ++j) {
        const int d = d0 + j;
        float* row = out + (((size_t)b * DD + d) * HH + h) * WW + w0;
        float4 o0 = make_float4(acc[0][j] * inv_c, acc[1][j] * inv_c,
                                acc[2][j] * inv_c, acc[3][j] * inv_c);
        float4 o1 = make_float4(acc[4][j] * inv_c, acc[5][j] * inv_c,
                                acc[6][j] * inv_c, acc[7][j] * inv_c);
        ((float4*)row)[0] = o0;
        ((float4*)row)[1] = o1;
    }
}

extern "C" void kernel_launch(void* const* d_in, const int* in_sizes, int n_in,
                              void* d_out, int out_size) {
    const float* x = (const float*)d_in[0];
    float* out = (float*)d_out;
    (void)in_sizes; (void)n_in; (void)out_size;

    cudaFuncSetAttribute(disp_corr_kernel,
                         cudaFuncAttributeMaxDynamicSharedMemorySize, SMEM_BYTES);
    disp_corr_kernel<<<BB * HH, NTHREADS, SMEM_BYTES>>>(x, out);
}

// round 6
// speedup vs baseline: 1.4289x; 1.4289x over previous
#include <cuda_runtime.h>

// Problem shape (fixed):
//   x: (B=4, C2=64, H=256, W=512) fp32 ; D=64 ; C=32
//   out[b,d,h,w] = (1/C) * sum_c L[b,c,h,w] * R[b,c,h,w-d]   (R zero-padded left)
//
// Design (round-2 experiment, re-submitted; broker timeouts rounds 2-5):
//   - CTA = one (b, h, w-half): covers w in [w_base, w_base+256), all 64 d.
//   - smem: L[32][256] (32 KB) + R[32][320] (40 KB) = 72 KB -> 2 CTAs/SM resident
//     (staging of one CTA overlaps compute of the other; 32 warps/SM).
//   - thread tile: 4(w) x 8(d). Lane LDS stride = 16 B -> conflict-free LDS.128.
//   - __launch_bounds__(512, 2) to force <=64 regs for dual residency.

#define CC   32
#define HH   256
#define WW   512
#define DD   64
#define WHALF 256
#define RPADF 64                  // left pad floats in R tile
#define RWID  (WHALF + RPADF)     // 320 floats per R row

#define NTHREADS 512
#define SMEM_BYTES ((CC * WHALF + CC * RWID) * 4)   // 73728

__global__ __launch_bounds__(NTHREADS, 2)
void disp_corr_kernel(const float* __restrict__ x, float* __restrict__ out) {
    extern __shared__ float smem[];
    float* Ls = smem;               // [CC][WHALF]
    float* Rs = smem + CC * WHALF;  // [CC][RWID]

    const int bx   = blockIdx.x;         // 0 .. 2*B*H-1
    const int half = bx & 1;
    const int bh   = bx >> 1;
    const int b    = bh >> 8;
    const int h    = bh & 255;
    const int tid  = threadIdx.x;
    const int w_base = half << 8;        // 0 or 256

    const size_t chw = (size_t)HH * WW;  // 131072
    // x[b, c, h, w] = x[ ((b*64 + c)*H + h)*W + w ]
    const float* xL = x + (((size_t)b * 64 + 0 ) * HH + h) * WW;
    const float* xR = x + (((size_t)b * 64 + CC) * HH + h) * WW;

    // ---- Stage L: 32 rows x 64 float4 (coalesced) ----
    for (int it = tid; it < CC * (WHALF / 4); it += NTHREADS) {
        const int c  = it >> 6;          // /64
        const int w4 = it & 63;          // %64
        ((float4*)(Ls + c * WHALF))[w4] =
            ((const float4*)(xL + (size_t)c * chw + w_base))[w4];
    }
    // ---- Stage R: 32 rows x 80 float4, covering s in [w_base-64, w_base+256) ----
    for (int it = tid; it < CC * (RWID / 4); it += NTHREADS) {
        const int c  = it / (RWID / 4);  // /80
        const int i4 = it - c * (RWID / 4);
        const int s4 = (w_base >> 2) - (RPADF / 4) + i4;   // global float4 index
        float4 v = make_float4(0.f, 0.f, 0.f, 0.f);
        if (s4 >= 0) v = ((const float4*)(xR + (size_t)c * chw))[s4];
        ((float4*)(Rs + c * RWID))[i4] = v;
    }
    __syncthreads();

    // ---- Each thread: 4(w) x 8(d) output tile ----
    // 512 threads * 32 outputs = 16384 = 64 d * 256 w  (exact cover)
    const int w0 = (tid & 63) << 2;      // 0..252 (local w)
    const int d0 = (tid >> 6) << 3;      // 0..56  (d constant within a warp)
    // R smem index for (w_local, d): w_local - d + RPADF.
    // Needed offsets: w0+i - (d0+j) + 64, i in [0,4), j in [0,8)  -> [w0-d0+57, w0-d0+67]
    const int rb = w0 - d0 + 56;         // multiple of 4 -> 16B aligned; rb in [0, 308]

    float4 acc[8];

    // ---- Channel 0: initialize acc with MUL (no FMA-onto-zero) ----
    {
        const float4 l = *(const float4*)(Ls + w0);
        const float4* rp = (const float4*)(Rs + rb);
        const float4 r0 = rp[0];
        const float4 r1 = rp[1];
        const float4 r2 = rp[2];
        const float r[12] = { r0.x, r0.y, r0.z, r0.w,
                              r1.x, r1.y, r1.z, r1.w,
                              r2.x, r2.y, r2.z, r2.w };
#pragma unroll
        for (int j = 0; j < 8; ++j) {
            acc[j].x = l.x * r[8  - j];
            acc[j].y = l.y * r[9  - j];
            acc[j].z = l.z * r[10 - j];
            acc[j].w = l.w * r[11 - j];
        }
    }

    for (int c = 1; c < CC; ++c) {
        const float4 l = *(const float4*)(Ls + c * WHALF + w0);
        const float4* rp = (const float4*)(Rs + c * RWID + rb);
        const float4 r0 = rp[0];
        const float4 r1 = rp[1];
        const float4 r2 = rp[2];
        const float r[12] = { r0.x, r0.y, r0.z, r0.w,
                              r1.x, r1.y, r1.z, r1.w,
                              r2.x, r2.y, r2.z, r2.w };
#pragma unroll
        for (int j = 0; j < 8; ++j) {
            // offset for lane-component i: (i - j + 8) relative to rb
            acc[j].x += l.x * r[8  - j];
            acc[j].y += l.y * r[9  - j];
            acc[j].z += l.z * r[10 - j];
            acc[j].w += l.w * r[11 - j];
        }
    }

    // ---- Write out[ ((b*D + d)*H + h)*W + w ] as float4 (coalesced per warp) ----
    const float inv_c = 1.0f / (float)CC;
#pragma unroll
    for (int j = 0; j < 8; ++j) {
        const int d = d0 + j;
        float* row = out + (((size_t)b * DD + d) * HH + h) * WW + w_base + w0;
        float4 o = make_float4(acc[j].x * inv_c, acc[j].y * inv_c,
                               acc[j].z * inv_c, acc[j].w * inv_c);
        *(float4*)row = o;
    }
}

extern "C" void kernel_launch(void* const* d_in, const int* in_sizes, int n_in,
                              void* d_out, int out_size) {
    const float* x = (const float*)d_in[0];
    float* out = (float*)d_out;
    (void)in_sizes; (void)n_in; (void)out_size;

    cudaFuncSetAttribute(disp_corr_kernel,
                         cudaFuncAttributeMaxDynamicSharedMemorySize, SMEM_BYTES);
    disp_corr_kernel<<<2 * 4 * HH, NTHREADS, SMEM_BYTES>>>(x, out);
}